// round 16
// baseline (speedup 1.0000x reference)
#include <cuda_runtime.h>
#include <cuda_bf16.h>

#define Bb   8
#define T    16
#define C    64
#define Hh   56
#define Ww   56
#define HW   3136          // 56*56
#define HW4  784           // HW/4
#define DIN  64            // 8*8 pooled
#define DOUT 32            // 2*d_t
#define NBC  512           // b*c
#define NCOL (NBC * HW4)   // 401408 float4 columns (= 1568 * 256)

// scratch: softmaxed attention [n][t][s], 512KB
__device__ float g_att[NBC * T * T];

// ---------------------------------------------------------------------------
// Kernel 1 (fused pool+att): one block per n = (b,c), 1024 threads / 32 warps.
// Warp (t, half) owns 4 bin-rows, accumulated into acc[4] with NO barriers
// between rounds -> 28 independent LDG.64 per lane in flight. Single smem
// dump + 32-lane reduce afterwards. Then q/k + logits + shuffle softmax.
// ---------------------------------------------------------------------------
__global__ __launch_bounds__(1024)
void pool_att_kernel(const float* __restrict__ x,
                     const float* __restrict__ Wq, const float* __restrict__ bq,
                     const float* __restrict__ Wk, const float* __restrict__ bk)
{
    const int n    = blockIdx.x;        // n = b*C + c
    const int b    = n >> 6;
    const int c    = n & 63;
    const int tid  = threadIdx.x;
    const int w    = tid >> 5;          // warp 0..31
    const int t    = w >> 1;            // slice 0..15
    const int half = w & 1;             // which 4 bin-rows
    const int lane = tid & 31;

    __shared__ float scol[32][4][58];        // per-warp,per-round col sums 29.7KB
    __shared__ float flat[T][DIN];           // pooled features
    __shared__ float sWq[DIN * DOUT];        // 8 KB
    __shared__ float sWk[DIN * DOUT];        // 8 KB
    __shared__ float sq[T][DOUT + 1];
    __shared__ float sk[T][DOUT + 1];

    // stage weights (overlaps with x loads across warps)
    for (int i = tid; i < DIN * DOUT; i += 1024) {
        sWq[i] = Wq[i];
        sWk[i] = Wk[i];
    }

    // ---- pool: all 4 rounds accumulated independently, loads front-batched
    const float* slice = x + ((size_t)(b * T + t) * C + c) * HW;
    if (lane < 28) {
        float2 acc[4];
        #pragma unroll
        for (int r = 0; r < 4; ++r)
            acc[r] = make_float2(0.f, 0.f);
        #pragma unroll
        for (int r = 0; r < 4; ++r) {
            const int d1 = half * 4 + r;
            const float2* rows = (const float2*)(slice + (7 * d1) * Ww);
            #pragma unroll
            for (int dh = 0; dh < 7; ++dh) {
                const float2 v = rows[dh * (Ww / 2) + lane];
                acc[r].x += v.x;
                acc[r].y += v.y;
            }
        }
        #pragma unroll
        for (int r = 0; r < 4; ++r)
            *(float2*)&scol[w][r][2 * lane] = acc[r];
    }
    __syncwarp();

    // 32-lane reduce: lane -> (round r2, bin col d2)
    {
        const int r2 = lane >> 3;            // 0..3
        const int d2 = lane & 7;             // 0..7
        const float* cs = &scol[w][r2][7 * d2];
        float a0 = cs[0] + cs[1];
        float a1 = cs[2] + cs[3];
        float a2 = cs[4] + cs[5];
        a0 += cs[6];
        flat[t][(half * 4 + r2) * 8 + d2] = (a0 + a1 + a2) * (1.f / 49.f);
    }
    __syncthreads();

    // ---- q = flat@Wq + bq ; k = flat@Wk + bk (threads 0..511) ----
    if (tid < 512) {
        const int tt = tid >> 5, j = tid & 31;
        float aq = bq[j];
        float ak = bk[j];
        #pragma unroll
        for (int d = 0; d < DIN; ++d) {
            const float f = flat[tt][d];
            aq = fmaf(f, sWq[d * DOUT + j], aq);
            ak = fmaf(f, sWk[d * DOUT + j], ak);
        }
        sq[tt][j] = aq;
        sk[tt][j] = ak;
    }
    __syncthreads();

    // ---- logits + shuffle softmax (threads 0..255) ----
    if (tid < 256) {
        const int i = tid >> 4, j = tid & 15;
        float s = 0.f;
        #pragma unroll
        for (int d = 0; d < DOUT; ++d)
            s = fmaf(sq[i][d], sk[j][d], s);
        s *= 0.25f;                          // 1/sqrt(16)

        float m = s;
        #pragma unroll
        for (int k = 8; k >= 1; k >>= 1)
            m = fmaxf(m, __shfl_xor_sync(0xffffffffu, m, k));
        float e = __expf(s - m);
        float ssum = e;
        #pragma unroll
        for (int k = 8; k >= 1; k >>= 1)
            ssum += __shfl_xor_sync(0xffffffffu, ssum, k);

        g_att[n * (T * T) + tid] = e * (1.f / ssum);
    }
}

// ---------------------------------------------------------------------------
// Kernel 2: out[b,t,c,:] = sum_s att[n,t,s] * x[b,s,c,:]
// __launch_bounds__(256,3), PDL pre-sync x loads, reversed-n, and now
// __stwt write-through stores: out lines don't allocate in L2, so x (103MB,
// fully touched by pool) stays L2-resident for av's reads.
// ---------------------------------------------------------------------------
__global__ __launch_bounds__(256, 3)
void av_kernel(const float* __restrict__ x, float* __restrict__ out)
{
    const int tid  = threadIdx.x;
    const int gid0 = blockIdx.x << 8;               // first column of block
    const int n0   = gid0 / HW4;                    // block spans n0 or n0+1

    const int gid = gid0 + tid;
    const int n   = gid / HW4;
    const int p4  = gid - n * HW4;
    const int m   = n - n0;
    const int rn  = NBC - 1 - n;                    // reversed n
    const int b   = rn >> 6;
    const int c   = rn & 63;

    const int stride_s = C * HW4;                   // float4 stride per t/s
    const int base     = (b * T * C + c) * HW4 + p4;
    const float4* xb = (const float4*)x + base;
    float4* ob = (float4*)out + base;

    // pre-sync: issue the 16 strided x loads (no dependency on att)
    float4 v[T];
    #pragma unroll
    for (int s = 0; s < T; ++s)
        v[s] = xb[s * stride_s];

    cudaGridDependencySynchronize();                // wait for g_att

    // stage att rows for the (at most) 2 reversed-n's this block touches
    __shared__ float satt[2][T * T];
    #pragma unroll
    for (int i = tid; i < 2 * T * T; i += 256) {
        const int mm  = i >> 8;
        const int idx = i & 255;
        const int nn  = n0 + mm;
        satt[mm][idx] = (nn < NBC) ? g_att[(NBC - 1 - nn) * (T * T) + idx] : 0.f;
    }
    __syncthreads();

    const float* arow = satt[m];
    #pragma unroll
    for (int t = 0; t < T; ++t) {
        float4 a = make_float4(0.f, 0.f, 0.f, 0.f);
        #pragma unroll
        for (int s = 0; s < T; ++s) {
            const float w = arow[t * T + s];
            a.x = fmaf(w, v[s].x, a.x);
            a.y = fmaf(w, v[s].y, a.y);
            a.z = fmaf(w, v[s].z, a.z);
            a.w = fmaf(w, v[s].w, a.w);
        }
        __stwt(&ob[t * stride_s], a);               // write-through store
    }
}

// ---------------------------------------------------------------------------
extern "C" void kernel_launch(void* const* d_in, const int* in_sizes, int n_in,
                              void* d_out, int out_size)
{
    const float* x  = (const float*)d_in[0];
    const float* Wq = (const float*)d_in[1];
    const float* bq = (const float*)d_in[2];
    const float* Wk = (const float*)d_in[3];
    const float* bk = (const float*)d_in[4];
    float* out = (float*)d_out;

    pool_att_kernel<<<NBC, 1024>>>(x, Wq, bq, Wk, bk);

    cudaLaunchAttribute attr[1];
    attr[0].id = cudaLaunchAttributeProgrammaticStreamSerialization;
    attr[0].val.programmaticStreamSerializationAllowed = 1;

    cudaLaunchConfig_t cfg = {};
    cfg.gridDim  = dim3(NCOL / 256);
    cfg.blockDim = dim3(256);
    cfg.dynamicSmemBytes = 0;
    cfg.stream = 0;
    cfg.attrs = attr;
    cfg.numAttrs = 1;
    cudaLaunchKernelEx(&cfg, av_kernel, x, out);
}